// round 16
// baseline (speedup 1.0000x reference)
#include <cuda_runtime.h>
#include <cuda_bf16.h>
#include <cuda_fp16.h>
#include <cstdint>
#include <math.h>

#define Bn  4
#define Sn  2048
#define En  1024
#define Hn  16
#define DKn 64
#define Mn  (Bn * Sn)   // 8192

// ==================== device global scratch ====================
__device__ __half g_Xf[Mn * En];                  // x fp16
__device__ __half g_Wf[4 * En * En];              // Wq,Wk,Wv,Wo fp16
__device__ __half g_Qf[Mn * En];                  // (B,H,S,DK) pre-scaled log2e/8
__device__ __half g_Kf[Mn * En];                  // (B,H,S,DK)
__device__ __half g_Vf[Mn * En];                  // (B,H,DK,S) d-major
__device__ __half g_Cf[Mn * En];                  // ctx (B,S,E) fp16

// ==================== helpers ====================
__device__ __forceinline__ uint32_t smem_to_u32(const void* p) {
    uint32_t a;
    asm("{ .reg .u64 t; cvta.to.shared.u64 t, %1; cvt.u32.u64 %0, t; }"
        : "=r"(a) : "l"(p));
    return a;
}
__device__ __forceinline__ void ldsm4(uint32_t addr, uint32_t r[4]) {
    asm volatile("ldmatrix.sync.aligned.m8n8.x4.shared.b16 {%0,%1,%2,%3}, [%4];"
                 : "=r"(r[0]), "=r"(r[1]), "=r"(r[2]), "=r"(r[3]) : "r"(addr));
}
__device__ __forceinline__ void mma16816h(float d[4], const uint32_t a[4],
                                          uint32_t b0, uint32_t b1) {
    asm volatile(
        "mma.sync.aligned.m16n8k16.row.col.f32.f16.f16.f32 "
        "{%0,%1,%2,%3}, {%4,%5,%6,%7}, {%8,%9}, {%0,%1,%2,%3};"
        : "+f"(d[0]), "+f"(d[1]), "+f"(d[2]), "+f"(d[3])
        : "r"(a[0]), "r"(a[1]), "r"(a[2]), "r"(a[3]), "r"(b0), "r"(b1));
}
// fp16-accumulator MMA (full-rate path) for QK^T
__device__ __forceinline__ void mma16816hh(uint32_t d[2], const uint32_t a[4],
                                           uint32_t b0, uint32_t b1) {
    asm volatile(
        "mma.sync.aligned.m16n8k16.row.col.f16.f16.f16.f16 "
        "{%0,%1}, {%2,%3,%4,%5}, {%6,%7}, {%0,%1};"
        : "+r"(d[0]), "+r"(d[1])
        : "r"(a[0]), "r"(a[1]), "r"(a[2]), "r"(a[3]), "r"(b0), "r"(b1));
}
#define CP16(saddr, gptr) \
    asm volatile("cp.async.cg.shared.global [%0], [%1], 16;" \
                 :: "r"(saddr), "l"(gptr))
#define CP_COMMIT() asm volatile("cp.async.commit_group;")
#define CP_WAIT0()  asm volatile("cp.async.wait_group 0;")
#define CP_WAIT1()  asm volatile("cp.async.wait_group 1;")
#define CP_WAIT2()  asm volatile("cp.async.wait_group 2;")

__device__ __forceinline__ uint32_t pack_f16x2(float a, float b) {
    uint32_t r;
    asm("cvt.rn.f16x2.f32 %0, %1, %2;" : "=r"(r) : "f"(b), "f"(a));
    return r;
}

// ==================== convert inputs to fp16 (1 launch, MLP=4) =============
#define NX4 (Mn * En / 4)     // 2097152
#define NW4 (En * En / 4)     // 262144 = 2^18
#define NTOT4 (NX4 + 4 * NW4) // 3145728
#define SPLIT_STRIDE (NTOT4 / 4)   // 786432

__global__ __launch_bounds__(256)
void split_all_kernel(const float* __restrict__ x,
                      const float* __restrict__ wq, const float* __restrict__ wk,
                      const float* __restrict__ wv, const float* __restrict__ wo)
{
    const int t = blockIdx.x * blockDim.x + threadIdx.x;
    float4 v[4];
    __half* dstp[4];
    int offp[4];
#pragma unroll
    for (int k = 0; k < 4; k++) {
        int i = t + k * SPLIT_STRIDE;
        const float* src; __half* dst; int off;
        if (i < NX4) { src = x; dst = g_Xf; off = i; }
        else {
            int j = i - NX4;
            int s = j >> 18;
            off = j & (NW4 - 1);
            src = (s == 0) ? wq : (s == 1) ? wk : (s == 2) ? wv : wo;
            dst = g_Wf + (size_t)s * En * En;
        }
        v[k] = ((const float4*)src)[off];
        dstp[k] = dst; offp[k] = off;
    }
#pragma unroll
    for (int k = 0; k < 4; k++) {
        ((__half2*)dstp[k])[offp[k] * 2 + 0] =
            __halves2half2(__float2half_rn(v[k].x), __float2half_rn(v[k].y));
        ((__half2*)dstp[k])[offp[k] * 2 + 1] =
            __halves2half2(__float2half_rn(v[k].z), __float2half_rn(v[k].w));
    }
}

// ==================== unified fp16 GEMM: Y = A @ W^T ====================
// 128x128 tile, 8 warps (wm2 x wn4), warp 64x32, BK=64.
// 3 circular buffers, prefetch 1, ONE barrier per chunk. 2 CTAs/SM.
#define QGSB 144                 // 64 fp16 = 128B + 16 pad
#define QGT  (128 * QGSB)        // 18432
#define QKV_SMEM (6 * QGT)       // 110592 (3 bufs x A,B)

#define QKV_ISSUE(buf, k0) do {                                             \
    _Pragma("unroll")                                                       \
    for (int _t = 0; _t < 2; _t++) {                                        \
        const __half* _src = (_t == 0) ? pA : pB;                           \
        uint32_t _db = sb + ((buf) * 2 + _t) * QGT;                         \
        _Pragma("unroll")                                                   \
        for (int _i = 0; _i < 4; _i++) {                                    \
            int _u = _i * 256 + tid; int _r = _u >> 3; int _c = _u & 7;     \
            CP16(_db + _r * QGSB + _c * 16,                                 \
                 _src + (size_t)_r * En + (k0) + _c * 8);                   \
        }                                                                   \
    }                                                                       \
    CP_COMMIT();                                                            \
} while (0)

__global__ __launch_bounds__(256, 2)
void gemm_f16(int mode, float* __restrict__ outp)
{
    extern __shared__ char sm[];
    const uint32_t sb = smem_to_u32(sm);
    const int tid = threadIdx.x, wid = tid >> 5, lane = tid & 31;
    const int wm = wid >> 2, wn = wid & 3;
    const int z = blockIdx.z;
    const int ws = (mode == 1) ? 3 : z;
    const int rowBase = blockIdx.y * 128, colBase = blockIdx.x * 128;

    const __half* __restrict__ pA =
        (mode == 0 ? g_Xf : g_Cf) + (size_t)rowBase * En;
    const __half* __restrict__ pB =
        g_Wf + (size_t)ws * En * En + (size_t)colBase * En;

    float acc[4][4][4];
#pragma unroll
    for (int a = 0; a < 4; a++)
#pragma unroll
        for (int b = 0; b < 4; b++)
#pragma unroll
            for (int c = 0; c < 4; c++) acc[a][b][c] = 0.f;

    const int rin = lane & 15;
    const int chf = lane >> 4;

    QKV_ISSUE(0, 0);
#pragma unroll 1
    for (int ch = 0; ch < 16; ch++) {
        const int buf = ch % 3;
        if (ch < 15) { QKV_ISSUE((ch + 1) % 3, (ch + 1) * 64); CP_WAIT1(); }
        else         { CP_WAIT0(); }
        __syncthreads();   // publishes chunk ch from ALL threads; WAR by induction
        const uint32_t aB = sb + (buf * 2 + 0) * QGT;
        const uint32_t bB = sb + (buf * 2 + 1) * QGT;

#pragma unroll
        for (int ks = 0; ks < 4; ks++) {
            uint32_t kf[2][4];
#pragma unroll
            for (int p = 0; p < 2; p++) {
                uint32_t off = (uint32_t)((wn * 32 + p * 16 + rin) * QGSB
                                          + (ks * 16 + chf * 8) * 2);
                ldsm4(bB + off, kf[p]);
            }
#pragma unroll
            for (int mt = 0; mt < 4; mt++) {
                uint32_t af[4];
                uint32_t off = (uint32_t)((wm * 64 + mt * 16 + rin) * QGSB
                                          + (ks * 16 + chf * 8) * 2);
                ldsm4(aB + off, af);
#pragma unroll
                for (int nt = 0; nt < 4; nt++) {
                    const int p = nt >> 1, e = nt & 1;
                    mma16816h(acc[mt][nt], af, kf[p][e], kf[p][2 + e]);
                }
            }
        }
    }
    __syncthreads();   // all ldsm reads done before any smem-reuse epilogue

    const int qr = lane >> 2, qc = (lane & 3) * 2;

    if (mode == 0 && z == 2) {
        // ---- V: transpose through smem, coalesced d-major stores ----
        __half* tsm = (__half*)sm;
        const int TS = 136;
#pragma unroll
        for (int mt = 0; mt < 4; mt++)
#pragma unroll
            for (int hf = 0; hf < 2; hf++) {
                const int ml = wm * 64 + mt * 16 + qr + hf * 8;
#pragma unroll
                for (int nt = 0; nt < 4; nt++) {
                    const int nl = wn * 32 + nt * 8 + qc;
                    tsm[(nl + 0) * TS + ml] =
                        __float2half_rn(acc[mt][nt][hf * 2 + 0]);
                    tsm[(nl + 1) * TS + ml] =
                        __float2half_rn(acc[mt][nt][hf * 2 + 1]);
                }
            }
        __syncthreads();
        const int n = tid >> 1, mh = tid & 1;
        const int b = rowBase >> 11, s0 = rowBase & (Sn - 1);
        const int h = (colBase + n) >> 6, d = (colBase + n) & 63;
        __half* dst = g_Vf + ((size_t)(b * Hn + h) * DKn + d) * Sn + s0 + mh * 64;
        const __half* srcp = tsm + n * TS + mh * 64;
#pragma unroll
        for (int j = 0; j < 8; j++)
            ((float4*)dst)[j] = ((const float4*)srcp)[j];
        return;
    }

    // Q pre-scale folds softmax 1/sqrt(dk) AND log2(e) for exp2-domain softmax
    const float oscale = (mode == 0 && z == 0) ? 0.125f * 1.44269504f : 1.0f;
#pragma unroll
    for (int mt = 0; mt < 4; mt++)
#pragma unroll
        for (int hf = 0; hf < 2; hf++) {
            const int m = rowBase + wm * 64 + mt * 16 + qr + hf * 8;
#pragma unroll
            for (int nt = 0; nt < 4; nt++) {
                const int n = colBase + wn * 32 + nt * 8 + qc;
                const float v0 = acc[mt][nt][hf * 2 + 0] * oscale;
                const float v1 = acc[mt][nt][hf * 2 + 1] * oscale;
                if (mode == 1) {
                    float2 o; o.x = v0; o.y = v1;
                    *(float2*)&outp[(size_t)m * En + n] = o;
                } else {
                    const int b = m >> 11, s = m & (Sn - 1);
                    const int h = n >> 6, d = n & 63;
                    size_t i0 = ((size_t)(b * Hn + h) * Sn + s) * DKn + d;
                    __half* dst = (z == 0) ? g_Qf : g_Kf;
                    *(__half2*)&dst[i0] = __halves2half2(__float2half_rn(v0),
                                                         __float2half_rn(v1));
                }
            }
        }
}

// ==================== MMA flash attention (warp-independent softmax) =======
// 8 warps: wm = wid&3 -> 32 q rows; kvh = wid>>2 -> private 64-kv half.
// 4 circular KV buffers, prefetch distance 2, ONE barrier per kv tile.
// QK^T in fp16-accumulator MMA (full-rate); softmax in exp2 domain (Q
// pre-scaled by log2e/8); PV in fp32-accumulator MMA.
#define QKSB 144
#define VSB  272
#define KBUF 18432
#define VBUF 17408
#define oQ 0
#define oK 18432                      // 4 x KBUF = 73728
#define oV 92160                      // 4 x VBUF = 69632
#define oRed 161792                   // redm[128], redl[128] f32
#define oStage 163840                 // 128*64 f32 = 32768
#define ATTN_SMEM 196608

#define ISSUE_KV(buf, kv) do {                                              \
    uint32_t _kb = sb + oK + (buf) * KBUF;                                  \
    uint32_t _vb = sb + oV + (buf) * VBUF;                                  \
    _Pragma("unroll")                                                       \
    for (int _i = 0; _i < 4; _i++) {                                        \
        int _u = _i * 256 + tid; int _r = _u >> 3; int _c = _u & 7;         \
        CP16(_kb + _r * QKSB + _c * 16,                                     \
             g_Kf + base + (size_t)((kv) + _r) * DKn + _c * 8);             \
    }                                                                       \
    _Pragma("unroll")                                                       \
    for (int _i = 0; _i < 4; _i++) {                                        \
        int _u = _i * 256 + tid; int _r = _u >> 4; int _c = _u & 15;        \
        CP16(_vb + _r * VSB + _c * 16,                                      \
             g_Vf + base + (size_t)_r * Sn + (kv) + _c * 8);                \
    }                                                                       \
    CP_COMMIT();                                                            \
} while (0)

__global__ __launch_bounds__(256, 1)
void attn_mma_kernel()
{
    extern __shared__ char sm[];
    const uint32_t sb = smem_to_u32(sm);
    float* redm = (float*)(sm + oRed);
    float* redl = (float*)(sm + oRed + 512);
    float* stage = (float*)(sm + oStage);

    const int tid = threadIdx.x, wid = tid >> 5, lane = tid & 31;
    const int wm = wid & 3, kvh = wid >> 2;
    const int q0 = blockIdx.x * 128;
    const int bh = blockIdx.y;
    const size_t base = (size_t)bh * Sn * DKn;

    const int rin = lane & 15;
    const int chf = lane >> 4;
    const int qr = lane >> 2, qc = (lane & 3) * 2;

    // Q tile (128 x 64 fp16), then KV tiles 0 and 1 (prefetch distance 2)
#pragma unroll
    for (int i = 0; i < 4; i++) {
        int u = i * 256 + tid; int r = u >> 3; int c = u & 7;
        CP16(sb + oQ + r * QKSB + c * 16,
             g_Qf + base + (size_t)(q0 + r) * DKn + c * 8);
    }
    CP_COMMIT();
    ISSUE_KV(0, 0);
    ISSUE_KV(1, 128);

    // hoist Q fragments: wait own Q group (KV0,KV1 may stay in flight),
    // barrier publishes everyone's Q
    CP_WAIT2();
    __syncthreads();
    uint32_t qf[4][2][4];
#pragma unroll
    for (int ks = 0; ks < 4; ks++)
#pragma unroll
        for (int mt = 0; mt < 2; mt++) {
            uint32_t off = (uint32_t)((wm * 32 + mt * 16 + rin) * QKSB
                                      + (ks * 16 + chf * 8) * 2);
            ldsm4(sb + oQ + off, qf[ks][mt]);
        }

    float acc_o[2][8][4];
    float m_st[2][2], l_st[2][2];
#pragma unroll
    for (int a = 0; a < 2; a++)
#pragma unroll
        for (int b = 0; b < 8; b++)
#pragma unroll
            for (int c = 0; c < 4; c++) acc_o[a][b][c] = 0.f;
#pragma unroll
    for (int a = 0; a < 2; a++)
#pragma unroll
        for (int b = 0; b < 2; b++) { m_st[a][b] = -1e30f; l_st[a][b] = 0.f; }

#pragma unroll 1
    for (int it = 0; it < 16; it++) {
        const int buf = it & 3;
        if (it < 14)      { ISSUE_KV((it + 2) & 3, (it + 2) * 128); CP_WAIT2(); }
        else if (it == 14) CP_WAIT1();
        else               CP_WAIT0();
        __syncthreads();   // publishes tile it from ALL threads; WAR by induction
        const uint32_t kB = sb + oK + buf * KBUF;
        const uint32_t vB = sb + oV + buf * VBUF;

        // ---- S = Q K^T, fp16 accumulators (full-rate MMA path) ----
        uint32_t sh[2][8][2];
#pragma unroll
        for (int a = 0; a < 2; a++)
#pragma unroll
            for (int b = 0; b < 8; b++) { sh[a][b][0] = 0u; sh[a][b][1] = 0u; }

#pragma unroll
        for (int ks = 0; ks < 4; ks++) {
            uint32_t kf[4][4];
#pragma unroll
            for (int p = 0; p < 4; p++) {
                uint32_t off = (uint32_t)((kvh * 64 + p * 16 + rin) * QKSB
                                          + (ks * 16 + chf * 8) * 2);
                ldsm4(kB + off, kf[p]);
            }
#pragma unroll
            for (int mt = 0; mt < 2; mt++)
#pragma unroll
                for (int nt = 0; nt < 8; nt++) {
                    const int p = nt >> 1, e = nt & 1;
                    mma16816hh(sh[mt][nt], qf[ks][mt], kf[p][e], kf[p][2 + e]);
                }
        }

        // convert to fp32 for softmax (d[0]={r,c0..1}, d[1]={r+8,c0..1})
        float s[2][8][4];
#pragma unroll
        for (int mt = 0; mt < 2; mt++)
#pragma unroll
            for (int nt = 0; nt < 8; nt++) {
                float2 lo = __half22float2(*(__half2*)&sh[mt][nt][0]);
                float2 hi = __half22float2(*(__half2*)&sh[mt][nt][1]);
                s[mt][nt][0] = lo.x; s[mt][nt][1] = lo.y;
                s[mt][nt][2] = hi.x; s[mt][nt][3] = hi.y;
            }

        // ---- warp-local online softmax (exp2 domain) ----
#pragma unroll
        for (int mt = 0; mt < 2; mt++)
#pragma unroll
            for (int hf = 0; hf < 2; hf++) {
                float mx = m_st[mt][hf];
#pragma unroll
                for (int nt = 0; nt < 8; nt++)
#pragma unroll
                    for (int e2 = 0; e2 < 2; e2++)
                        mx = fmaxf(mx, s[mt][nt][hf * 2 + e2]);
                mx = fmaxf(mx, __shfl_xor_sync(0xffffffffu, mx, 1));
                mx = fmaxf(mx, __shfl_xor_sync(0xffffffffu, mx, 2));
                const float alpha = exp2f(m_st[mt][hf] - mx);
                m_st[mt][hf] = mx;
                float sum = 0.f;
#pragma unroll
                for (int nt = 0; nt < 8; nt++)
#pragma unroll
                    for (int e2 = 0; e2 < 2; e2++) {
                        float p = exp2f(s[mt][nt][hf * 2 + e2] - mx);
                        s[mt][nt][hf * 2 + e2] = p;
                        sum += p;
                    }
                sum += __shfl_xor_sync(0xffffffffu, sum, 1);
                sum += __shfl_xor_sync(0xffffffffu, sum, 2);
                l_st[mt][hf] = l_st[mt][hf] * alpha + sum;
#pragma unroll
                for (int nt = 0; nt < 8; nt++) {
                    acc_o[mt][nt][hf * 2 + 0] *= alpha;
                    acc_o[mt][nt][hf * 2 + 1] *= alpha;
                }
            }

        // ---- O += P @ V (fp32 accumulators) ----
#pragma unroll
        for (int kc = 0; kc < 4; kc++) {
            uint32_t pa[2][4];
#pragma unroll
            for (int mt = 0; mt < 2; mt++) {
                const float* s0 = s[mt][2 * kc];
                const float* s1 = s[mt][2 * kc + 1];
                pa[mt][0] = pack_f16x2(s0[0], s0[1]);
                pa[mt][1] = pack_f16x2(s0[2], s0[3]);
                pa[mt][2] = pack_f16x2(s1[0], s1[1]);
                pa[mt][3] = pack_f16x2(s1[2], s1[3]);
            }
            uint32_t vf[4][4];
#pragma unroll
            for (int p = 0; p < 4; p++) {
                uint32_t off = (uint32_t)((p * 16 + rin) * VSB
                                          + (kvh * 64 + kc * 16 + chf * 8) * 2);
                ldsm4(vB + off, vf[p]);
            }
#pragma unroll
            for (int mt = 0; mt < 2; mt++)
#pragma unroll
                for (int nt = 0; nt < 8; nt++) {
                    const int p = nt >> 1, e = nt & 1;
                    mma16816h(acc_o[mt][nt], pa[mt], vf[p][e], vf[p][2 + e]);
                }
        }
    }

    // ---- merge the two kv halves (warps w and w+4) ----
    __syncthreads();
    if (kvh == 0) {
#pragma unroll
        for (int mt = 0; mt < 2; mt++)
#pragma unroll
            for (int hf = 0; hf < 2; hf++) {
                const int q = wm * 32 + mt * 16 + qr + hf * 8;
                if ((lane & 3) == 0) {
                    redm[q] = m_st[mt][hf];
                    redl[q] = l_st[mt][hf];
                }
#pragma unroll
                for (int nt = 0; nt < 8; nt++) {
                    float2 v;
                    v.x = acc_o[mt][nt][hf * 2 + 0];
                    v.y = acc_o[mt][nt][hf * 2 + 1];
                    *(float2*)&stage[q * 64 + nt * 8 + qc] = v;
                }
            }
    }
    __syncthreads();
    if (kvh == 1) {
        const int b = bh >> 4, h = bh & 15;
#pragma unroll
        for (int mt = 0; mt < 2; mt++)
#pragma unroll
            for (int hf = 0; hf < 2; hf++) {
                const int q = wm * 32 + mt * 16 + qr + hf * 8;
                const float m0 = redm[q], l0 = redl[q];
                const float m1 = m_st[mt][hf], l1 = l_st[mt][hf];
                const float mno = fmaxf(m0, m1);
                const float w0 = exp2f(m0 - mno), w1 = exp2f(m1 - mno);
                const float rinv = 1.f / (l0 * w0 + l1 * w1);
#pragma unroll
                for (int nt = 0; nt < 8; nt++) {
                    float2 prev = *(const float2*)&stage[q * 64 + nt * 8 + qc];
                    float v0 = (prev.x * w0 + acc_o[mt][nt][hf * 2 + 0] * w1) * rinv;
                    float v1 = (prev.y * w0 + acc_o[mt][nt][hf * 2 + 1] * w1) * rinv;
                    size_t idx = ((size_t)b * Sn + q0 + q) * En + h * DKn + nt * 8 + qc;
                    *(__half2*)&g_Cf[idx] =
                        __halves2half2(__float2half_rn(v0), __float2half_rn(v1));
                }
            }
    }
}

// ==================== launch ====================
extern "C" void kernel_launch(void* const* d_in, const int* in_sizes, int n_in,
                              void* d_out, int out_size)
{
    (void)in_sizes; (void)n_in; (void)out_size;
    const float* x  = (const float*)d_in[0];
    const float* Wq = (const float*)d_in[1];
    const float* Wk = (const float*)d_in[2];
    const float* Wv = (const float*)d_in[3];
    const float* Wo = (const float*)d_in[4];
    float* out = (float*)d_out;

    cudaFuncSetAttribute(gemm_f16,
                         cudaFuncAttributeMaxDynamicSharedMemorySize, QKV_SMEM);
    cudaFuncSetAttribute(attn_mma_kernel,
                         cudaFuncAttributeMaxDynamicSharedMemorySize, ATTN_SMEM);

    split_all_kernel<<<SPLIT_STRIDE / 256, 256>>>(x, Wq, Wk, Wv, Wo);

    dim3 gq(En / 128, Mn / 128, 3);
    gemm_f16<<<gq, 256, QKV_SMEM>>>(0, nullptr);

    dim3 ga(Sn / 128, Bn * Hn);
    attn_mma_kernel<<<ga, 256, ATTN_SMEM>>>();

    dim3 go(En / 128, Mn / 128);
    gemm_f16<<<go, 256, QKV_SMEM>>>(1, out);
}

// round 17
// speedup vs baseline: 1.0177x; 1.0177x over previous
#include <cuda_runtime.h>
#include <cuda_bf16.h>
#include <cuda_fp16.h>
#include <cstdint>
#include <math.h>

#define Bn  4
#define Sn  2048
#define En  1024
#define Hn  16
#define DKn 64
#define Mn  (Bn * Sn)   // 8192

// ==================== device global scratch ====================
__device__ __half g_Xf[Mn * En];                  // x fp16
__device__ __half g_Wf[4 * En * En];              // Wq,Wk,Wv,Wo fp16
__device__ __half g_Qf[Mn * En];                  // (B,H,S,DK) pre-scaled log2e/8
__device__ __half g_Kf[Mn * En];                  // (B,H,S,DK)
__device__ __half g_Vf[Mn * En];                  // (B,H,DK,S) d-major
__device__ __half g_Cf[Mn * En];                  // ctx (B,S,E) fp16

// ==================== helpers ====================
__device__ __forceinline__ uint32_t smem_to_u32(const void* p) {
    uint32_t a;
    asm("{ .reg .u64 t; cvta.to.shared.u64 t, %1; cvt.u32.u64 %0, t; }"
        : "=r"(a) : "l"(p));
    return a;
}
__device__ __forceinline__ void ldsm4(uint32_t addr, uint32_t r[4]) {
    asm volatile("ldmatrix.sync.aligned.m8n8.x4.shared.b16 {%0,%1,%2,%3}, [%4];"
                 : "=r"(r[0]), "=r"(r[1]), "=r"(r[2]), "=r"(r[3]) : "r"(addr));
}
__device__ __forceinline__ void mma16816h(float d[4], const uint32_t a[4],
                                          uint32_t b0, uint32_t b1) {
    asm volatile(
        "mma.sync.aligned.m16n8k16.row.col.f32.f16.f16.f32 "
        "{%0,%1,%2,%3}, {%4,%5,%6,%7}, {%8,%9}, {%0,%1,%2,%3};"
        : "+f"(d[0]), "+f"(d[1]), "+f"(d[2]), "+f"(d[3])
        : "r"(a[0]), "r"(a[1]), "r"(a[2]), "r"(a[3]), "r"(b0), "r"(b1));
}
#define CP16(saddr, gptr) \
    asm volatile("cp.async.cg.shared.global [%0], [%1], 16;" \
                 :: "r"(saddr), "l"(gptr))
#define CP_COMMIT() asm volatile("cp.async.commit_group;")
#define CP_WAIT0()  asm volatile("cp.async.wait_group 0;")
#define CP_WAIT1()  asm volatile("cp.async.wait_group 1;")
#define CP_WAIT2()  asm volatile("cp.async.wait_group 2;")

__device__ __forceinline__ uint32_t pack_f16x2(float a, float b) {
    uint32_t r;
    asm("cvt.rn.f16x2.f32 %0, %1, %2;" : "=r"(r) : "f"(b), "f"(a));
    return r;
}

// ==================== convert inputs to fp16 (1 launch, MLP=4) =============
#define NX4 (Mn * En / 4)     // 2097152
#define NW4 (En * En / 4)     // 262144 = 2^18
#define NTOT4 (NX4 + 4 * NW4) // 3145728
#define SPLIT_STRIDE (NTOT4 / 4)   // 786432

__global__ __launch_bounds__(256)
void split_all_kernel(const float* __restrict__ x,
                      const float* __restrict__ wq, const float* __restrict__ wk,
                      const float* __restrict__ wv, const float* __restrict__ wo)
{
    const int t = blockIdx.x * blockDim.x + threadIdx.x;
    float4 v[4];
    __half* dstp[4];
    int offp[4];
#pragma unroll
    for (int k = 0; k < 4; k++) {
        int i = t + k * SPLIT_STRIDE;
        const float* src; __half* dst; int off;
        if (i < NX4) { src = x; dst = g_Xf; off = i; }
        else {
            int j = i - NX4;
            int s = j >> 18;
            off = j & (NW4 - 1);
            src = (s == 0) ? wq : (s == 1) ? wk : (s == 2) ? wv : wo;
            dst = g_Wf + (size_t)s * En * En;
        }
        v[k] = ((const float4*)src)[off];
        dstp[k] = dst; offp[k] = off;
    }
#pragma unroll
    for (int k = 0; k < 4; k++) {
        ((__half2*)dstp[k])[offp[k] * 2 + 0] =
            __halves2half2(__float2half_rn(v[k].x), __float2half_rn(v[k].y));
        ((__half2*)dstp[k])[offp[k] * 2 + 1] =
            __halves2half2(__float2half_rn(v[k].z), __float2half_rn(v[k].w));
    }
}

// ==================== unified fp16 GEMM: Y = A @ W^T ====================
// 128x128 tile, 8 warps (wm2 x wn4), warp 64x32, BK=64.
// 3 circular buffers, prefetch 1, ONE barrier per chunk:
//   issue(ch+1) -> wait own -> sync -> compute(ch).
// WAR sound: issue target (ch+1)%3 == (ch-2)%3 was read at iter ch-2 and all
// warps passed the iter ch-1 barrier since. 110 KB smem -> 2 CTAs/SM.
#define QGSB 144                 // 64 fp16 = 128B + 16 pad
#define QGT  (128 * QGSB)        // 18432
#define QKV_SMEM (6 * QGT)       // 110592 (3 bufs x A,B)

#define QKV_ISSUE(bofs, k0) do {                                            \
    _Pragma("unroll")                                                       \
    for (int _t = 0; _t < 2; _t++) {                                        \
        const __half* _src = (_t == 0) ? pA : pB;                           \
        uint32_t _db = sb + (bofs) + _t * QGT;                              \
        _Pragma("unroll")                                                   \
        for (int _i = 0; _i < 4; _i++) {                                    \
            int _u = _i * 256 + tid; int _r = _u >> 3; int _c = _u & 7;     \
            CP16(_db + _r * QGSB + _c * 16,                                 \
                 _src + (size_t)_r * En + (k0) + _c * 8);                   \
        }                                                                   \
    }                                                                       \
    CP_COMMIT();                                                            \
} while (0)

__global__ __launch_bounds__(256, 2)
void gemm_f16(int mode, float* __restrict__ outp)
{
    extern __shared__ char sm[];
    const uint32_t sb = smem_to_u32(sm);
    const int tid = threadIdx.x, wid = tid >> 5, lane = tid & 31;
    const int wm = wid >> 2, wn = wid & 3;
    const int z = blockIdx.z;
    const int ws = (mode == 1) ? 3 : z;
    const int rowBase = blockIdx.y * 128, colBase = blockIdx.x * 128;

    const __half* __restrict__ pA =
        (mode == 0 ? g_Xf : g_Cf) + (size_t)rowBase * En;
    const __half* __restrict__ pB =
        g_Wf + (size_t)ws * En * En + (size_t)colBase * En;

    float acc[4][4][4];
#pragma unroll
    for (int a = 0; a < 4; a++)
#pragma unroll
        for (int b = 0; b < 4; b++)
#pragma unroll
            for (int c = 0; c < 4; c++) acc[a][b][c] = 0.f;

    const int rin = lane & 15;
    const int chf = lane >> 4;

    // rotating buffer byte-offsets (strength-reduced % 3)
    uint32_t bo_cur = 0, bo_nxt = 2 * QGT, bo_far = 4 * QGT;

    QKV_ISSUE(bo_cur, 0);
#pragma unroll 1
    for (int ch = 0; ch < 16; ch++) {
        if (ch < 15) { QKV_ISSUE(bo_nxt, (ch + 1) * 64); CP_WAIT1(); }
        else         { CP_WAIT0(); }
        __syncthreads();   // publishes chunk ch from ALL threads; WAR by induction
        const uint32_t aB = sb + bo_cur;
        const uint32_t bB = aB + QGT;
        // rotate for next iteration
        uint32_t t0 = bo_cur; bo_cur = bo_nxt; bo_nxt = bo_far; bo_far = t0;

#pragma unroll
        for (int ks = 0; ks < 4; ks++) {
            uint32_t kf[2][4];
#pragma unroll
            for (int p = 0; p < 2; p++) {
                uint32_t off = (uint32_t)((wn * 32 + p * 16 + rin) * QGSB
                                          + (ks * 16 + chf * 8) * 2);
                ldsm4(bB + off, kf[p]);
            }
#pragma unroll
            for (int mt = 0; mt < 4; mt++) {
                uint32_t af[4];
                uint32_t off = (uint32_t)((wm * 64 + mt * 16 + rin) * QGSB
                                          + (ks * 16 + chf * 8) * 2);
                ldsm4(aB + off, af);
#pragma unroll
                for (int nt = 0; nt < 4; nt++) {
                    const int p = nt >> 1, e = nt & 1;
                    mma16816h(acc[mt][nt], af, kf[p][e], kf[p][2 + e]);
                }
            }
        }
    }
    __syncthreads();   // all ldsm reads done before any smem-reuse epilogue

    const int qr = lane >> 2, qc = (lane & 3) * 2;

    if (mode == 0 && z == 2) {
        // ---- V: transpose through smem, coalesced d-major stores ----
        __half* tsm = (__half*)sm;
        const int TS = 136;
#pragma unroll
        for (int mt = 0; mt < 4; mt++)
#pragma unroll
            for (int hf = 0; hf < 2; hf++) {
                const int ml = wm * 64 + mt * 16 + qr + hf * 8;
#pragma unroll
                for (int nt = 0; nt < 4; nt++) {
                    const int nl = wn * 32 + nt * 8 + qc;
                    tsm[(nl + 0) * TS + ml] =
                        __float2half_rn(acc[mt][nt][hf * 2 + 0]);
                    tsm[(nl + 1) * TS + ml] =
                        __float2half_rn(acc[mt][nt][hf * 2 + 1]);
                }
            }
        __syncthreads();
        const int n = tid >> 1, mh = tid & 1;
        const int b = rowBase >> 11, s0 = rowBase & (Sn - 1);
        const int h = (colBase + n) >> 6, d = (colBase + n) & 63;
        __half* dst = g_Vf + ((size_t)(b * Hn + h) * DKn + d) * Sn + s0 + mh * 64;
        const __half* srcp = tsm + n * TS + mh * 64;
#pragma unroll
        for (int j = 0; j < 8; j++)
            ((float4*)dst)[j] = ((const float4*)srcp)[j];
        return;
    }

    // Q pre-scale folds softmax 1/sqrt(dk) AND log2(e) for exp2-domain softmax
    const float oscale = (mode == 0 && z == 0) ? 0.125f * 1.44269504f : 1.0f;
#pragma unroll
    for (int mt = 0; mt < 4; mt++)
#pragma unroll
        for (int hf = 0; hf < 2; hf++) {
            const int m = rowBase + wm * 64 + mt * 16 + qr + hf * 8;
#pragma unroll
            for (int nt = 0; nt < 4; nt++) {
                const int n = colBase + wn * 32 + nt * 8 + qc;
                const float v0 = acc[mt][nt][hf * 2 + 0] * oscale;
                const float v1 = acc[mt][nt][hf * 2 + 1] * oscale;
                if (mode == 1) {
                    float2 o; o.x = v0; o.y = v1;
                    *(float2*)&outp[(size_t)m * En + n] = o;
                } else {
                    const int b = m >> 11, s = m & (Sn - 1);
                    const int h = n >> 6, d = n & 63;
                    size_t i0 = ((size_t)(b * Hn + h) * Sn + s) * DKn + d;
                    __half* dst = (z == 0) ? g_Qf : g_Kf;
                    *(__half2*)&dst[i0] = __halves2half2(__float2half_rn(v0),
                                                         __float2half_rn(v1));
                }
            }
        }
}

// ==================== MMA flash attention (warp-independent softmax) =======
// 8 warps: wm = wid&3 -> 32 q rows; kvh = wid>>2 -> private 64-kv half.
// 4 circular KV buffers, prefetch distance 2, ONE barrier per kv tile:
//   issue(it+2) -> wait own (<=2 groups) -> sync -> compute(it).
// Scores in log2 domain (Q pre-scaled by log2e/8) -> bare exp2f softmax.
#define QKSB 144
#define VSB  272
#define KBUF 18432
#define VBUF 17408
#define oQ 0
#define oK 18432                      // 4 x KBUF = 73728
#define oV 92160                      // 4 x VBUF = 69632
#define oRed 161792                   // redm[128], redl[128] f32
#define oStage 163840                 // 128*64 f32 = 32768
#define ATTN_SMEM 196608

#define ISSUE_KV(buf, kv) do {                                              \
    uint32_t _kb = sb + oK + (buf) * KBUF;                                  \
    uint32_t _vb = sb + oV + (buf) * VBUF;                                  \
    _Pragma("unroll")                                                       \
    for (int _i = 0; _i < 4; _i++) {                                        \
        int _u = _i * 256 + tid; int _r = _u >> 3; int _c = _u & 7;         \
        CP16(_kb + _r * QKSB + _c * 16,                                     \
             g_Kf + base + (size_t)((kv) + _r) * DKn + _c * 8);             \
    }                                                                       \
    _Pragma("unroll")                                                       \
    for (int _i = 0; _i < 4; _i++) {                                        \
        int _u = _i * 256 + tid; int _r = _u >> 4; int _c = _u & 15;        \
        CP16(_vb + _r * VSB + _c * 16,                                      \
             g_Vf + base + (size_t)_r * Sn + (kv) + _c * 8);                \
    }                                                                       \
    CP_COMMIT();                                                            \
} while (0)

__global__ __launch_bounds__(256, 1)
void attn_mma_kernel()
{
    extern __shared__ char sm[];
    const uint32_t sb = smem_to_u32(sm);
    float* redm = (float*)(sm + oRed);
    float* redl = (float*)(sm + oRed + 512);
    float* stage = (float*)(sm + oStage);

    const int tid = threadIdx.x, wid = tid >> 5, lane = tid & 31;
    const int wm = wid & 3, kvh = wid >> 2;
    const int q0 = blockIdx.x * 128;
    const int bh = blockIdx.y;
    const size_t base = (size_t)bh * Sn * DKn;

    const int rin = lane & 15;
    const int chf = lane >> 4;
    const int qr = lane >> 2, qc = (lane & 3) * 2;

    // Q tile (128 x 64 fp16), then KV tiles 0 and 1 (prefetch distance 2)
#pragma unroll
    for (int i = 0; i < 4; i++) {
        int u = i * 256 + tid; int r = u >> 3; int c = u & 7;
        CP16(sb + oQ + r * QKSB + c * 16,
             g_Qf + base + (size_t)(q0 + r) * DKn + c * 8);
    }
    CP_COMMIT();
    ISSUE_KV(0, 0);
    ISSUE_KV(1, 128);

    // hoist Q fragments: wait own Q group (KV0,KV1 may stay in flight),
    // barrier publishes everyone's Q
    CP_WAIT2();
    __syncthreads();
    uint32_t qf[4][2][4];
#pragma unroll
    for (int ks = 0; ks < 4; ks++)
#pragma unroll
        for (int mt = 0; mt < 2; mt++) {
            uint32_t off = (uint32_t)((wm * 32 + mt * 16 + rin) * QKSB
                                      + (ks * 16 + chf * 8) * 2);
            ldsm4(sb + oQ + off, qf[ks][mt]);
        }

    float acc_o[2][8][4];
    float m_st[2][2], l_st[2][2];
#pragma unroll
    for (int a = 0; a < 2; a++)
#pragma unroll
        for (int b = 0; b < 8; b++)
#pragma unroll
            for (int c = 0; c < 4; c++) acc_o[a][b][c] = 0.f;
#pragma unroll
    for (int a = 0; a < 2; a++)
#pragma unroll
        for (int b = 0; b < 2; b++) { m_st[a][b] = -1e30f; l_st[a][b] = 0.f; }

#pragma unroll 1
    for (int it = 0; it < 16; it++) {
        const int buf = it & 3;
        if (it < 14)      { ISSUE_KV((it + 2) & 3, (it + 2) * 128); CP_WAIT2(); }
        else if (it == 14) CP_WAIT1();
        else               CP_WAIT0();
        __syncthreads();   // publishes tile it from ALL threads; WAR by induction
        const uint32_t kB = sb + oK + buf * KBUF;
        const uint32_t vB = sb + oV + buf * VBUF;

        // ---- S = Q K^T over this warp's 64-kv slice (log2 domain) ----
        float s[2][8][4];
#pragma unroll
        for (int a = 0; a < 2; a++)
#pragma unroll
            for (int b = 0; b < 8; b++)
#pragma unroll
                for (int c = 0; c < 4; c++) s[a][b][c] = 0.f;

#pragma unroll
        for (int ks = 0; ks < 4; ks++) {
            uint32_t kf[4][4];
#pragma unroll
            for (int p = 0; p < 4; p++) {
                uint32_t off = (uint32_t)((kvh * 64 + p * 16 + rin) * QKSB
                                          + (ks * 16 + chf * 8) * 2);
                ldsm4(kB + off, kf[p]);
            }
#pragma unroll
            for (int mt = 0; mt < 2; mt++)
#pragma unroll
                for (int nt = 0; nt < 8; nt++) {
                    const int p = nt >> 1, e = nt & 1;
                    mma16816h(s[mt][nt], qf[ks][mt], kf[p][e], kf[p][2 + e]);
                }
        }

        // ---- warp-local online softmax (exp2 domain) ----
#pragma unroll
        for (int mt = 0; mt < 2; mt++)
#pragma unroll
            for (int hf = 0; hf < 2; hf++) {
                float mx = m_st[mt][hf];
#pragma unroll
                for (int nt = 0; nt < 8; nt++)
#pragma unroll
                    for (int e2 = 0; e2 < 2; e2++)
                        mx = fmaxf(mx, s[mt][nt][hf * 2 + e2]);
                mx = fmaxf(mx, __shfl_xor_sync(0xffffffffu, mx, 1));
                mx = fmaxf(mx, __shfl_xor_sync(0xffffffffu, mx, 2));
                const float alpha = exp2f(m_st[mt][hf] - mx);
                m_st[mt][hf] = mx;
                float sum = 0.f;
#pragma unroll
                for (int nt = 0; nt < 8; nt++)
#pragma unroll
                    for (int e2 = 0; e2 < 2; e2++) {
                        float p = exp2f(s[mt][nt][hf * 2 + e2] - mx);
                        s[mt][nt][hf * 2 + e2] = p;
                        sum += p;
                    }
                sum += __shfl_xor_sync(0xffffffffu, sum, 1);
                sum += __shfl_xor_sync(0xffffffffu, sum, 2);
                l_st[mt][hf] = l_st[mt][hf] * alpha + sum;
#pragma unroll
                for (int nt = 0; nt < 8; nt++) {
                    acc_o[mt][nt][hf * 2 + 0] *= alpha;
                    acc_o[mt][nt][hf * 2 + 1] *= alpha;
                }
            }

        // ---- O += P @ V over this warp's 64-kv slice ----
#pragma unroll
        for (int kc = 0; kc < 4; kc++) {
            uint32_t pa[2][4];
#pragma unroll
            for (int mt = 0; mt < 2; mt++) {
                const float* s0 = s[mt][2 * kc];
                const float* s1 = s[mt][2 * kc + 1];
                pa[mt][0] = pack_f16x2(s0[0], s0[1]);
                pa[mt][1] = pack_f16x2(s0[2], s0[3]);
                pa[mt][2] = pack_f16x2(s1[0], s1[1]);
                pa[mt][3] = pack_f16x2(s1[2], s1[3]);
            }
            uint32_t vf[4][4];
#pragma unroll
            for (int p = 0; p < 4; p++) {
                uint32_t off = (uint32_t)((p * 16 + rin) * VSB
                                          + (kvh * 64 + kc * 16 + chf * 8) * 2);
                ldsm4(vB + off, vf[p]);
            }
#pragma unroll
            for (int mt = 0; mt < 2; mt++)
#pragma unroll
                for (int nt = 0; nt < 8; nt++) {
                    const int p = nt >> 1, e = nt & 1;
                    mma16816h(acc_o[mt][nt], pa[mt], vf[p][e], vf[p][2 + e]);
                }
        }
    }

    // ---- merge the two kv halves (warps w and w+4) ----
    __syncthreads();
    if (kvh == 0) {
#pragma unroll
        for (int mt = 0; mt < 2; mt++)
#pragma unroll
            for (int hf = 0; hf < 2; hf++) {
                const int q = wm * 32 + mt * 16 + qr + hf * 8;
                if ((lane & 3) == 0) {
                    redm[q] = m_st[mt][hf];
                    redl[q] = l_st[mt][hf];
                }
#pragma unroll
                for (int nt = 0; nt < 8; nt++) {
                    float2 v;
                    v.x = acc_o[mt][nt][hf * 2 + 0];
                    v.y = acc_o[mt][nt][hf * 2 + 1];
                    *(float2*)&stage[q * 64 + nt * 8 + qc] = v;
                }
            }
    }
    __syncthreads();
    if (kvh == 1) {
        const int b = bh >> 4, h = bh & 15;
#pragma unroll
        for (int mt = 0; mt < 2; mt++)
#pragma unroll
            for (int hf = 0; hf < 2; hf++) {
                const int q = wm * 32 + mt * 16 + qr + hf * 8;
                const float m0 = redm[q], l0 = redl[q];
                const float m1 = m_st[mt][hf], l1 = l_st[mt][hf];
                const float mno = fmaxf(m0, m1);
                const float w0 = exp2f(m0 - mno), w1 = exp2f(m1 - mno);
                const float rinv = 1.f / (l0 * w0 + l1 * w1);
#pragma unroll
                for (int nt = 0; nt < 8; nt++) {
                    float2 prev = *(const float2*)&stage[q * 64 + nt * 8 + qc];
                    float v0 = (prev.x * w0 + acc_o[mt][nt][hf * 2 + 0] * w1) * rinv;
                    float v1 = (prev.y * w0 + acc_o[mt][nt][hf * 2 + 1] * w1) * rinv;
                    size_t idx = ((size_t)b * Sn + q0 + q) * En + h * DKn + nt * 8 + qc;
                    *(__half2*)&g_Cf[idx] =
                        __halves2half2(__float2half_rn(v0), __float2half_rn(v1));
                }
            }
    }
}

// ==================== launch ====================
extern "C" void kernel_launch(void* const* d_in, const int* in_sizes, int n_in,
                              void* d_out, int out_size)
{
    (void)in_sizes; (void)n_in; (void)out_size;
    const float* x  = (const float*)d_in[0];
    const float* Wq = (const float*)d_in[1];
    const float* Wk = (const float*)d_in[2];
    const float* Wv = (const float*)d_in[3];
    const float* Wo = (const float*)d_in[4];
    float* out = (float*)d_out;

    cudaFuncSetAttribute(gemm_f16,
                         cudaFuncAttributeMaxDynamicSharedMemorySize, QKV_SMEM);
    cudaFuncSetAttribute(attn_mma_kernel,
                         cudaFuncAttributeMaxDynamicSharedMemorySize, ATTN_SMEM);

    split_all_kernel<<<SPLIT_STRIDE / 256, 256>>>(x, Wq, Wk, Wv, Wo);

    dim3 gq(En / 128, Mn / 128, 3);
    gemm_f16<<<gq, 256, QKV_SMEM>>>(0, nullptr);

    dim3 ga(Sn / 128, Bn * Hn);
    attn_mma_kernel<<<ga, 256, ATTN_SMEM>>>();

    dim3 go(En / 128, Mn / 128);
    gemm_f16<<<go, 256, QKV_SMEM>>>(1, out);
}